// round 2
// baseline (speedup 1.0000x reference)
#include <cuda_runtime.h>
#include <cuda_bf16.h>

#define NLEV  256
#define NBINS 4096

// Scratch LUT: lut[b] = count(u < fmaf(b, w, lo))  (may undercount by <=1; safe)
__device__ __align__(16) short g_lut[NBINS];

__global__ void build_lut_kernel(const float* __restrict__ u)
{
    int b = blockIdx.x * blockDim.x + threadIdx.x;   // 0..4095
    if (b >= NBINS) return;
    float lo = u[0];
    float hi = u[NLEV - 1];
    float w  = (hi - lo) * (1.0f / NBINS);
    float bs = fmaf((float)b, w, lo);

    // counting lower-bound: pos = count(u < bs), capped at 255 (undercount-safe)
    int pos = 0;
    #pragma unroll
    for (int s = 128; s >= 1; s >>= 1) {
        if (u[pos + s - 1] < bs) pos += s;
    }
    g_lut[b] = (short)pos;
}

__global__ void __launch_bounds__(256, 6)
agc_quant_kernel(const float4* __restrict__ in4,
                 const float4* __restrict__ mn4,
                 const float*  __restrict__ uvals,
                 float* __restrict__ out_dq,   // d_out[0 .. n)
                 float* __restrict__ out_sym,  // d_out[n .. 2n)
                 int n4, int n)
{
    __shared__ float su[NLEV];                 // 1 KB codebook
    __shared__ __align__(16) short slut[NBINS]; // 8 KB LUT

    const int tid = threadIdx.x;

    // Fill shared codebook + LUT (vectorized 16B copies for the LUT)
    if (tid < NLEV) su[tid] = uvals[tid];
    {
        const int4* src = reinterpret_cast<const int4*>(g_lut);
        int4*       dst = reinterpret_cast<int4*>(slut);
        for (int i = tid; i < NBINS * (int)sizeof(short) / 16; i += blockDim.x)
            dst[i] = src[i];
    }
    __syncthreads();

    const float lo    = su[0];
    const float hi    = su[NLEV - 1];
    const float w     = (hi - lo) * (1.0f / NBINS);
    const float inv_w = 1.0f / w;

    const int stride = gridDim.x * blockDim.x;

    for (int i = blockIdx.x * blockDim.x + tid; i < n4; i += stride) {
        float4 x = in4[i];
        float4 m = mn4[i];

        float v[4];
        v[0] = x.x - m.x; v[1] = x.y - m.y; v[2] = x.z - m.z; v[3] = x.w - m.w;

        // Bin index with floor-guard so that fmaf(b,w,lo) <= v (exactness).
        int bb[4];
        #pragma unroll
        for (int j = 0; j < 4; j++) {
            int b = (int)((v[j] - lo) * inv_w);
            b = b < 0 ? 0 : (b > NBINS - 1 ? NBINS - 1 : b);
            if (fmaf((float)b, w, lo) > v[j]) b = (b > 0) ? b - 1 : 0;
            bb[j] = b;
        }

        // LUT seed (4 independent LDS in flight), then tiny forward scan.
        int jv[4];
        #pragma unroll
        for (int j = 0; j < 4; j++) jv[j] = slut[bb[j]];
        #pragma unroll
        for (int j = 0; j < 4; j++) {
            int p = jv[j];
            while (p < NLEV && su[p] < v[j]) ++p;   // expected ~0.06 iters
            jv[j] = p;                              // = count(u < v) exactly
        }

        float dq[4], sy[4];
        #pragma unroll
        for (int j = 0; j < 4; j++) {
            int c = jv[j];
            c = c < 1 ? 1 : (c > NLEV - 1 ? NLEV - 1 : c);
            float left  = su[c - 1];
            float right = su[c];
            bool tl = fabsf(v[j] - left) <= fabsf(v[j] - right);
            sy[j] = (float)(tl ? c - 1 : c);
            dq[j] = tl ? left : right;
        }
        dq[0] += m.x; dq[1] += m.y; dq[2] += m.z; dq[3] += m.w;

        reinterpret_cast<float4*>(out_dq)[i]  = make_float4(dq[0], dq[1], dq[2], dq[3]);
        reinterpret_cast<float4*>(out_sym)[i] = make_float4(sy[0], sy[1], sy[2], sy[3]);
    }

    // Scalar tail (n % 4 != 0) — block 0 only.
    if (blockIdx.x == 0) {
        const float* in1 = reinterpret_cast<const float*>(in4);
        const float* mn1 = reinterpret_cast<const float*>(mn4);
        for (int i = n4 * 4 + tid; i < n; i += blockDim.x) {
            float vv = in1[i] - mn1[i];
            int b = (int)((vv - lo) * inv_w);
            b = b < 0 ? 0 : (b > NBINS - 1 ? NBINS - 1 : b);
            if (fmaf((float)b, w, lo) > vv) b = (b > 0) ? b - 1 : 0;
            int p = slut[b];
            while (p < NLEV && su[p] < vv) ++p;
            int c = p < 1 ? 1 : (p > NLEV - 1 ? NLEV - 1 : p);
            float left  = su[c - 1];
            float right = su[c];
            bool tl = fabsf(vv - left) <= fabsf(vv - right);
            out_sym[i] = (float)(tl ? c - 1 : c);
            out_dq[i]  = (tl ? left : right) + mn1[i];
        }
    }
}

extern "C" void kernel_launch(void* const* d_in, const int* in_sizes, int n_in,
                              void* d_out, int out_size)
{
    const float* inputs = (const float*)d_in[0];
    const float* means  = (const float*)d_in[1];
    const float* uvals  = (const float*)d_in[2];
    float* out = (float*)d_out;

    const int n  = out_size / 2;
    const int n4 = n / 4;

    float* out_dq  = out;
    float* out_sym = out + n;

    build_lut_kernel<<<NBINS / 256, 256>>>(uvals);

    const int threads = 256;
    int blocks = 1184;                       // ~8 waves of grid-stride work
    int maxb = (n4 + threads - 1) / threads;
    if (blocks > maxb && maxb > 0) blocks = maxb;
    if (blocks < 1) blocks = 1;

    agc_quant_kernel<<<blocks, threads>>>(
        (const float4*)inputs, (const float4*)means, uvals,
        out_dq, out_sym, n4, n);
}